// round 8
// baseline (speedup 1.0000x reference)
#include <cuda_runtime.h>
#include <stdint.h>

// SpikeFP32GELUExact: [B,S,32] bit-pulses -> decode fp32 -> exact fp64 tanh-GELU
// -> round fp32 -> encode [B,S,32] bit-pulses. Bit 0 = MSB.
//
// Warp-cooperative layout: each warp owns 32 consecutive elements (a 32x32 bit
// matrix = 4KB). Loads/stores are fully coalesced 128B LDG.32/STG.32; the bit
// transpose is done with __ballot_sync + __brev (pack) and __shfl_sync (unpack).
// GELU math mirrors the reference's fp64 op sequence exactly: every mul/add is
// individually rounded (no FMA contraction), division is IEEE-correct, exp is
// CUDA's <1-ulp double exp.

__global__ void __launch_bounds__(256)
spike_gelu_kernel(const uint32_t* __restrict__ xu,
                  uint32_t* __restrict__ outu,
                  int n_elem)
{
    const int lane        = threadIdx.x & 31;
    const int warp_global = (blockIdx.x * blockDim.x + threadIdx.x) >> 5;
    const int base        = warp_global * 32;           // first element this warp owns
    if (base >= n_elem) return;

    const size_t off = (size_t)base * 32;               // word offset of the 32x32 block

    // ---- Load: lane l reads bit-position l of element (base+i). 128B coalesced. ----
    uint32_t v[32];
#pragma unroll
    for (int i = 0; i < 32; i++) {
        v[i] = xu[off + (size_t)i * 32 + lane];         // 0x00000000 or 0x3F800000
    }

    // ---- Transpose via ballot: after brev, bit l (MSB-first) lands correctly. ----
    uint32_t myu = 0;
#pragma unroll
    for (int i = 0; i < 32; i++) {
        unsigned b = __ballot_sync(0xffffffffu, v[i] != 0u);
        uint32_t u = __brev(b);
        if (lane == i) myu = u;
    }

    // ---- Exact GELU, fp64, mirroring reference rounding step-for-step. ----
    const float  xf = __uint_as_float(myu);
    const double x  = (double)xf;

    double x2    = __dmul_rn(x, x);                     // x*x
    double x3    = __dmul_rn(x2, x);                    // (x*x)*x
    double inner = __dadd_rn(x, __dmul_rn(0.044715, x3));
    double two_z = __dmul_rn(2.0, __dmul_rn(0.7978845608028654, inner));
    double e     = exp(two_z);                          // fp64 exp (<1 ulp)
    double th    = __ddiv_rn(__dadd_rn(e, -1.0), __dadd_rn(e, 1.0));
    double y     = __dmul_rn(0.5, __dmul_rn(x, __dadd_rn(1.0, th)));

    const uint32_t uy = __float_as_uint(__double2float_rn(y));

    // ---- Store: broadcast element i's word to all lanes; lane l writes bit l. ----
#pragma unroll
    for (int i = 0; i < 32; i++) {
        uint32_t ui  = __shfl_sync(0xffffffffu, uy, i);
        uint32_t bit = (ui >> (31 - lane)) & 1u;
        outu[off + (size_t)i * 32 + lane] = bit ? 0x3F800000u : 0u;  // 1.0f or 0.0f
    }
}

extern "C" void kernel_launch(void* const* d_in, const int* in_sizes, int n_in,
                              void* d_out, int out_size)
{
    const uint32_t* x   = (const uint32_t*)d_in[0];
    uint32_t*       out = (uint32_t*)d_out;

    const int n_elem  = in_sizes[0] / 32;               // 1024*4096 = 4,194,304
    const int threads = 256;                            // 8 warps = 256 elements/block
    const int blocks  = (n_elem + 255) / 256;

    spike_gelu_kernel<<<blocks, threads>>>(x, out, n_elem);
}

// round 9
// speedup vs baseline: 1.6403x; 1.6403x over previous
#include <cuda_runtime.h>
#include <stdint.h>

// SpikeFP32GELUExact: [B,S,32] bit-pulses -> decode fp32 -> exact fp64 tanh-GELU
// -> round fp32 -> encode [B,S,32] bit-pulses. Bit 0 = MSB.
//
// Warp-cooperative layout: each warp owns 32 consecutive elements (a 32x32 bit
// matrix = 4KB). Loads/stores are fully coalesced 128B LDG.32/STG.32; the bit
// transpose is done with __ballot_sync + __brev (pack) and __shfl_sync (unpack).
// GELU math mirrors the reference's fp64 op sequence exactly: every mul/add is
// individually rounded (no FMA contraction), division is IEEE-correct, exp is
// CUDA's <1-ulp double exp.

__global__ void __launch_bounds__(256)
spike_gelu_kernel(const uint32_t* __restrict__ xu,
                  uint32_t* __restrict__ outu,
                  int n_elem)
{
    const int lane        = threadIdx.x & 31;
    const int warp_global = (blockIdx.x * blockDim.x + threadIdx.x) >> 5;
    const int base        = warp_global * 32;           // first element this warp owns
    if (base >= n_elem) return;

    const size_t off = (size_t)base * 32;               // word offset of the 32x32 block

    // ---- Load: lane l reads bit-position l of element (base+i). 128B coalesced. ----
    uint32_t v[32];
#pragma unroll
    for (int i = 0; i < 32; i++) {
        v[i] = xu[off + (size_t)i * 32 + lane];         // 0x00000000 or 0x3F800000
    }

    // ---- Transpose via ballot: after brev, bit l (MSB-first) lands correctly. ----
    uint32_t myu = 0;
#pragma unroll
    for (int i = 0; i < 32; i++) {
        unsigned b = __ballot_sync(0xffffffffu, v[i] != 0u);
        uint32_t u = __brev(b);
        if (lane == i) myu = u;
    }

    // ---- Exact GELU, fp64, mirroring reference rounding step-for-step. ----
    const float  xf = __uint_as_float(myu);
    const double x  = (double)xf;

    double x2    = __dmul_rn(x, x);                     // x*x
    double x3    = __dmul_rn(x2, x);                    // (x*x)*x
    double inner = __dadd_rn(x, __dmul_rn(0.044715, x3));
    double two_z = __dmul_rn(2.0, __dmul_rn(0.7978845608028654, inner));
    double e     = exp(two_z);                          // fp64 exp (<1 ulp)
    double th    = __ddiv_rn(__dadd_rn(e, -1.0), __dadd_rn(e, 1.0));
    double y     = __dmul_rn(0.5, __dmul_rn(x, __dadd_rn(1.0, th)));

    const uint32_t uy = __float_as_uint(__double2float_rn(y));

    // ---- Store: broadcast element i's word to all lanes; lane l writes bit l. ----
#pragma unroll
    for (int i = 0; i < 32; i++) {
        uint32_t ui  = __shfl_sync(0xffffffffu, uy, i);
        uint32_t bit = (ui >> (31 - lane)) & 1u;
        outu[off + (size_t)i * 32 + lane] = bit ? 0x3F800000u : 0u;  // 1.0f or 0.0f
    }
}

extern "C" void kernel_launch(void* const* d_in, const int* in_sizes, int n_in,
                              void* d_out, int out_size)
{
    const uint32_t* x   = (const uint32_t*)d_in[0];
    uint32_t*       out = (uint32_t*)d_out;

    const int n_elem  = in_sizes[0] / 32;               // 1024*4096 = 4,194,304
    const int threads = 256;                            // 8 warps = 256 elements/block
    const int blocks  = (n_elem + 255) / 256;

    spike_gelu_kernel<<<blocks, threads>>>(x, out, n_elem);
}